// round 9
// baseline (speedup 1.0000x reference)
#include <cuda_runtime.h>
#include <stdint.h>

// Problem constants (fixed by the reference)
#define N_POI    10000
#define V_VOCAB  20000
#define BS       6400          // B*S = 64*100
#define N_VEC    (N_POI / 4)   // 2500 float4 per row
#define CHUNKS   5             // chunks per row
#define CHUNK_V  (N_VEC / CHUNKS)  // 500 float4 per chunk
#define BIG_INV  (1.0f / 9999999.99f)

__device__ __forceinline__ float4 recip_mask(float4 v) {
    float4 o;
    o.x = (v.x == 0.0f) ? BIG_INV : __fdividef(1.0f, v.x);
    o.y = (v.y == 0.0f) ? BIG_INV : __fdividef(1.0f, v.y);
    o.z = (v.z == 0.0f) ? BIG_INV : __fdividef(1.0f, v.z);
    o.w = (v.w == 0.0f) ? BIG_INV : __fdividef(1.0f, v.w);
    return o;
}

// ---------------------------------------------------------------------------
// Fine-grained fused kernel: one block per (row, chunk-of-500-float4).
// grid = BS * CHUNKS = 32000 blocks of 256 threads; per-block time ~2.6us,
// so the final-wave tail is ~5x shorter than with whole-row blocks, while
// the HW scheduler's work-stealing keeps SMs balanced.
//
// Index resolution is two warp-uniform loads (inputs_poi -> venueid2coor),
// L2-hot after the first wave; every thread issues them itself (broadcast
// coalesces to 1 transaction/warp) so there is no barrier.
//
// Index dtype auto-detected: int64 LE values in [0,10000) have zero upper
// 32-bit words; 16 consecutive zero upper-words on int32 data ~= prob 1e-64.
//
// Reads use the default cache policy (L2 dedups duplicate gathered rows);
// stores use __stcs (output is never re-read) to keep L2 for the read set.
// ---------------------------------------------------------------------------
__global__ void __launch_bounds__(256)
fused_gather_recip(const void* __restrict__ v2c,
                   const void* __restrict__ poi,
                   const float* __restrict__ mat,
                   float* __restrict__ out) {
    const int orow  = blockIdx.x / CHUNKS;
    const int chunk = blockIdx.x % CHUNKS;

    // dtype detection (L1-broadcast loads, warp-uniform)
    bool is64 = true;
    {
        const unsigned long long* p = (const unsigned long long*)v2c;
        #pragma unroll
        for (int i = 0; i < 16; i++)
            if ((p[i] >> 32) != 0ull) { is64 = false; break; }
    }

    // resolve venueid2coor[inputs_poi[orow]] (warp-uniform, L2-hot)
    int srow;
    if (is64) {
        long long vid = ((const long long*)poi)[orow];
        srow = (int)((const long long*)v2c)[vid];
    } else {
        int vid = ((const int*)poi)[orow];
        srow = ((const int*)v2c)[vid];
    }

    const float4* __restrict__ src =
        (const float4*)(mat + (long long)srow * N_POI) + chunk * CHUNK_V;
    float4* __restrict__ dst =
        (float4*)(out + (long long)orow * N_POI) + chunk * CHUNK_V;

    // CHUNK_V = 500 = 256 + 244. Both loads issued up front (MLP=2).
    const int c0 = threadIdx.x;
    const int c1 = c0 + 256;
    const bool p1 = (c1 < CHUNK_V);
    float4 v0 = src[c0];
    float4 v1;
    if (p1) v1 = src[c1];
    __stcs(&dst[c0], recip_mask(v0));
    if (p1) __stcs(&dst[c1], recip_mask(v1));
}

// ---------------------------------------------------------------------------
// Input order (setup_inputs dict order):
//   d_in[0] = venueid2coor        [V_VOCAB]       int64/int32 (detected)
//   d_in[1] = inputs_poi          [B*S]           int64/int32 (same dtype)
//   d_in[2] = poi_distance_matrix [N_POI*N_POI]   float32
// out: [B, S, N_POI] float32
// ---------------------------------------------------------------------------
extern "C" void kernel_launch(void* const* d_in, const int* in_sizes, int n_in,
                              void* d_out, int out_size) {
    const void*  v2c = d_in[0];
    const void*  poi = d_in[1];
    const float* mat = (const float*)d_in[2];
    float*       out = (float*)d_out;

    fused_gather_recip<<<BS * CHUNKS, 256>>>(v2c, poi, mat, out);
}

// round 10
// speedup vs baseline: 1.1357x; 1.1357x over previous
#include <cuda_runtime.h>
#include <stdint.h>

// Problem constants (fixed by the reference)
#define N_POI    10000
#define V_VOCAB  20000
#define BS       6400            // B*S = 64*100
#define N_VEC    (N_POI / 4)     // 2500 float4 per row
#define CHUNKS   2               // halves per row
#define CHUNK_V  (N_VEC / CHUNKS)// 1250 float4 per chunk
#define BIG_INV  (1.0f / 9999999.99f)

__device__ __forceinline__ float4 recip_mask(float4 v) {
    float4 o;
    o.x = (v.x == 0.0f) ? BIG_INV : __fdividef(1.0f, v.x);
    o.y = (v.y == 0.0f) ? BIG_INV : __fdividef(1.0f, v.y);
    o.z = (v.z == 0.0f) ? BIG_INV : __fdividef(1.0f, v.z);
    o.w = (v.w == 0.0f) ? BIG_INV : __fdividef(1.0f, v.w);
    return o;
}

// ---------------------------------------------------------------------------
// Half-row fused kernel: one block per (row, half). grid = 12800 x 256.
// Same inner structure as the best whole-row kernel (4 independent float4
// loads in flight, default-policy reads so L2 dedups duplicate gathered
// rows, __stcs evict-first writes), but half-row granularity shrinks the
// final-wave tail from ~60% idle of a 13us wave to ~20% of a 6.5us wave.
//
// Index resolution: two warp-uniform loads (inputs_poi -> venueid2coor),
// broadcast-coalesced, L2-hot after the first wave. No barrier, no smem.
// Index dtype auto-detected: int64 LE values in [0,10000) have zero upper
// 32-bit words; 16 consecutive zero upper-words on int32 data ~ prob 1e-64.
// ---------------------------------------------------------------------------
__global__ void __launch_bounds__(256)
fused_gather_recip(const void* __restrict__ v2c,
                   const void* __restrict__ poi,
                   const float* __restrict__ mat,
                   float* __restrict__ out) {
    const int orow  = blockIdx.x >> 1;        // row
    const int chunk = blockIdx.x & 1;         // half

    // dtype detection (L1-broadcast loads, warp-uniform)
    bool is64 = true;
    {
        const unsigned long long* p = (const unsigned long long*)v2c;
        #pragma unroll
        for (int i = 0; i < 16; i++)
            if ((p[i] >> 32) != 0ull) { is64 = false; break; }
    }

    // resolve venueid2coor[inputs_poi[orow]] (warp-uniform, L2-hot)
    int srow;
    if (is64) {
        long long vid = ((const long long*)poi)[orow];
        srow = (int)((const long long*)v2c)[vid];
    } else {
        int vid = ((const int*)poi)[orow];
        srow = ((const int*)v2c)[vid];
    }

    const float4* __restrict__ src =
        (const float4*)(mat + (long long)srow * N_POI) + chunk * CHUNK_V;
    float4* __restrict__ dst =
        (float4*)(out + (long long)orow * N_POI) + chunk * CHUNK_V;

    // CHUNK_V = 1250 = 4*256 + 226. Bulk: 4 loads batched (MLP=4), then a
    // predicated remainder.
    const int c = threadIdx.x;
    float4 v0 = src[c];
    float4 v1 = src[c + 256];
    float4 v2 = src[c + 512];
    float4 v3 = src[c + 768];
    __stcs(&dst[c],       recip_mask(v0));
    __stcs(&dst[c + 256], recip_mask(v1));
    __stcs(&dst[c + 512], recip_mask(v2));
    __stcs(&dst[c + 768], recip_mask(v3));

    if (c < CHUNK_V - 1024) {                 // 226 remainder lanes
        float4 vr = src[c + 1024];
        __stcs(&dst[c + 1024], recip_mask(vr));
    }
}

// ---------------------------------------------------------------------------
// Input order (setup_inputs dict order):
//   d_in[0] = venueid2coor        [V_VOCAB]       int64/int32 (detected)
//   d_in[1] = inputs_poi          [B*S]           int64/int32 (same dtype)
//   d_in[2] = poi_distance_matrix [N_POI*N_POI]   float32
// out: [B, S, N_POI] float32
// ---------------------------------------------------------------------------
extern "C" void kernel_launch(void* const* d_in, const int* in_sizes, int n_in,
                              void* d_out, int out_size) {
    const void*  v2c = d_in[0];
    const void*  poi = d_in[1];
    const float* mat = (const float*)d_in[2];
    float*       out = (float*)d_out;

    fused_gather_recip<<<BS * CHUNKS, 256>>>(v2c, poi, mat, out);
}